// round 4
// baseline (speedup 1.0000x reference)
#include <cuda_runtime.h>
#include <math.h>

// Problem constants
#define TN    8192
#define LOGN  13
#define HIDN  64
#define BN    8
#define CINN  32
#define COUTN 32
#define CTOTN 1024   // COUT*CIN

// ---------------- device scratch (allocation-free rule: __device__ globals) ----
__device__ float2 d_tw[TN / 2];                 // twiddles exp(-2*pi*i*k/N)
__device__ float  d_h2t[HIDN * TN];             // h2 transposed: [j][t]
__device__ float2 d_G[HIDN * TN];               // FFT_t(h2): [j][f]
__device__ float2 d_Hf[(size_t)CTOTN * TN];     // filter spectra: [(o*32+i)][f]
__device__ float2 d_Xf[(size_t)(BN * CINN) * TN];   // x spectra: [(b*32+i)][f]
__device__ float2 d_Yf[(size_t)(BN * COUTN) * TN];  // result spectra: [(b*32+o)][f]

// ---------------- twiddle table -------------------------------------------------
__global__ void k_twiddle() {
    int k = blockIdx.x * blockDim.x + threadIdx.x;
    if (k < TN / 2) {
        float s, c;
        sincospif(-2.0f * (float)k / (float)TN, &s, &c);
        d_tw[k] = make_float2(c, s);
    }
}

// ---------------- MLP: h2[t][j] = gelu(gelu(pos*w1+b1) @ w2 + b2) ---------------
__global__ void k_mlp(const float* __restrict__ w1, const float* __restrict__ b1,
                      const float* __restrict__ w2, const float* __restrict__ b2) {
    __shared__ float h1[HIDN];
    int t = blockIdx.x;
    int j = threadIdx.x;  // 64 threads
    float pos = (float)t * (1.0f / (float)(TN - 1));
    float z = pos * w1[j] + b1[j];
    h1[j] = 0.5f * z * (1.0f + erff(z * 0.7071067811865476f));
    __syncthreads();
    float acc = b2[j];
#pragma unroll
    for (int k = 0; k < HIDN; k++) acc += h1[k] * w2[k * HIDN + j];
    float h2 = 0.5f * acc * (1.0f + erff(acc * 0.7071067811865476f));
    d_h2t[j * TN + t] = h2;  // transposed store so FFT rows are contiguous
}

// ---------------- shared-memory radix-2 FFT core (8192 pts, 512 threads) --------
__device__ __forceinline__ void fft_stages(float2* s, int tid, bool inv) {
    for (int p = 0; p < LOGN; p++) {
        int half = 1 << p;
#pragma unroll
        for (int u = 0; u < (TN / 2) / 512; u++) {
            int k  = tid + u * 512;
            int j  = k & (half - 1);
            int i0 = ((k >> p) << (p + 1)) + j;
            int i1 = i0 + half;
            float2 w = d_tw[j << (LOGN - 1 - p)];
            float wy = inv ? -w.y : w.y;
            float2 bv = s[i1];
            float2 tv = make_float2(bv.x * w.x - bv.y * wy,
                                    bv.x * wy + bv.y * w.x);
            float2 av = s[i0];
            s[i0] = make_float2(av.x + tv.x, av.y + tv.y);
            s[i1] = make_float2(av.x - tv.x, av.y - tv.y);
        }
        __syncthreads();
    }
}

// forward FFT of real rows of x -> d_Xf
__global__ void k_fft_x(const float* __restrict__ x) {
    extern __shared__ float2 s[];
    int tid = threadIdx.x;
    const float* row = x + (size_t)blockIdx.x * TN;
#pragma unroll
    for (int u = 0; u < TN / 512; u++) {
        int idx = tid + u * 512;
        int r = __brev(idx) >> (32 - LOGN);
        s[r] = make_float2(row[idx], 0.0f);
    }
    __syncthreads();
    fft_stages(s, tid, false);
    float2* o = d_Xf + (size_t)blockIdx.x * TN;
#pragma unroll
    for (int u = 0; u < TN / 512; u++) { int idx = tid + u * 512; o[idx] = s[idx]; }
}

// forward FFT of real rows of h2t -> d_G  (only 64 transforms!)
__global__ void k_fft_g() {
    extern __shared__ float2 s[];
    int tid = threadIdx.x;
    const float* row = d_h2t + (size_t)blockIdx.x * TN;
#pragma unroll
    for (int u = 0; u < TN / 512; u++) {
        int idx = tid + u * 512;
        int r = __brev(idx) >> (32 - LOGN);
        s[r] = make_float2(row[idx], 0.0f);
    }
    __syncthreads();
    fft_stages(s, tid, false);
    float2* o = d_G + (size_t)blockIdx.x * TN;
#pragma unroll
    for (int u = 0; u < TN / 512; u++) { int idx = tid + u * 512; o[idx] = s[idx]; }
}

// inverse FFT of d_Yf rows -> real out (+bias)
__global__ void k_fft_inv(float* __restrict__ out, const float* __restrict__ bias) {
    extern __shared__ float2 s[];
    int tid = threadIdx.x;
    const float2* row = d_Yf + (size_t)blockIdx.x * TN;
#pragma unroll
    for (int u = 0; u < TN / 512; u++) {
        int idx = tid + u * 512;
        int r = __brev(idx) >> (32 - LOGN);
        s[r] = row[idx];
    }
    __syncthreads();
    fft_stages(s, tid, true);
    float bo = bias[blockIdx.x & (COUTN - 1)];
    const float sc = 1.0f / (float)TN;
    float* o = out + (size_t)blockIdx.x * TN;
#pragma unroll
    for (int u = 0; u < TN / 512; u++) {
        int idx = tid + u * 512;
        o[idx] = s[idx].x * sc + bo;
    }
}

// ---------------- complex GEMM: Hf[c][f] = sum_j w3[j][c] * G[j][f] -------------
// grid: (TN/128, CTOTN/64), 256 threads. smem = 64*64*4 + 64*128*8 = 81920 B.
__global__ void k_cgemm(const float* __restrict__ w3) {
    extern __shared__ float smraw[];
    float*  w3s = smraw;                          // [64][64]  w3s[k][c]
    float2* Gs  = (float2*)(smraw + 64 * 64);     // [64][128] Gs[k][f]
    int f0 = blockIdx.x * 128;
    int c0 = blockIdx.y * 64;
    int tid = threadIdx.x;
    for (int m = tid; m < 64 * 64; m += 256) {
        int k = m >> 6, c = m & 63;
        w3s[m] = w3[k * CTOTN + c0 + c];
    }
    for (int m = tid; m < 64 * 128; m += 256) {
        int j = m >> 7, f = m & 127;
        Gs[m] = d_G[(size_t)j * TN + f0 + f];
    }
    __syncthreads();
    int tx = tid & 15;   // f-tile: 8 freqs at tx*8
    int ty = tid >> 4;   // c-tile: 4 chans at ty*4
    float2 acc[4][8];
#pragma unroll
    for (int cc = 0; cc < 4; cc++)
#pragma unroll
        for (int ff = 0; ff < 8; ff++) acc[cc][ff] = make_float2(0.f, 0.f);

    for (int k = 0; k < 64; k++) {
        float4 av = *(const float4*)&w3s[k * 64 + ty * 4];
        float a[4] = {av.x, av.y, av.z, av.w};
        float4 g4[4];
        const float4* gp = (const float4*)&Gs[k * 128 + tx * 8];
#pragma unroll
        for (int q = 0; q < 4; q++) g4[q] = gp[q];
        const float2* g = (const float2*)g4;
#pragma unroll
        for (int cc = 0; cc < 4; cc++)
#pragma unroll
            for (int ff = 0; ff < 8; ff++) {
                acc[cc][ff].x += a[cc] * g[ff].x;
                acc[cc][ff].y += a[cc] * g[ff].y;
            }
    }
#pragma unroll
    for (int cc = 0; cc < 4; cc++) {
        int c = c0 + ty * 4 + cc;
        float2* dst = d_Hf + (size_t)c * TN + f0 + tx * 8;
#pragma unroll
        for (int ff = 0; ff < 8; ff++) dst[ff] = acc[cc][ff];
    }
}

// DC fixup: FFT of constant b3 contributes N*b3[c] at f=0 only
__global__ void k_fixup(const float* __restrict__ b3) {
    int c = blockIdx.x * blockDim.x + threadIdx.x;
    if (c < CTOTN) d_Hf[(size_t)c * TN].x += (float)TN * b3[c];
}

// ---------------- frequency-domain contraction ---------------------------------
// Y[b,o,f] = sum_i X[b,i,f] * Hf[o*32+i, f]   (complex mult, 16 freqs per block)
__global__ void k_contract() {
    __shared__ float2 Xs[16 * 257];   // Xs[fl*257 + (b*32+i)], padded stride
    int f0 = blockIdx.x * 16;
    int tid = threadIdx.x;            // 256
    for (int m = tid; m < 256 * 16; m += 256) {
        int c = m >> 4, fl = m & 15;
        Xs[fl * 257 + c] = d_Xf[(size_t)c * TN + f0 + fl];
    }
    __syncthreads();
    int b = tid >> 5, o = tid & 31;
    float2 acc[16];
#pragma unroll
    for (int fl = 0; fl < 16; fl++) acc[fl] = make_float2(0.f, 0.f);

    for (int i = 0; i < CINN; i++) {
        const float4* hrow = (const float4*)(d_Hf + (size_t)(o * CINN + i) * TN + f0);
        float4 hv[8];
#pragma unroll
        for (int q = 0; q < 8; q++) hv[q] = hrow[q];
        const float2* h = (const float2*)hv;
#pragma unroll
        for (int fl = 0; fl < 16; fl++) {
            float2 xv = Xs[fl * 257 + b * CINN + i];
            acc[fl].x += xv.x * h[fl].x - xv.y * h[fl].y;
            acc[fl].y += xv.x * h[fl].y + xv.y * h[fl].x;
        }
    }
    float2* y = d_Yf + (size_t)(b * COUTN + o) * TN + f0;
#pragma unroll
    for (int fl = 0; fl < 16; fl++) y[fl] = acc[fl];
}

// ---------------- launch ---------------------------------------------------------
extern "C" void kernel_launch(void* const* d_in, const int* in_sizes, int n_in,
                              void* d_out, int out_size) {
    const float* x    = (const float*)d_in[0];
    const float* w1   = (const float*)d_in[1];
    const float* b1   = (const float*)d_in[2];
    const float* w2   = (const float*)d_in[3];
    const float* b2   = (const float*)d_in[4];
    const float* w3   = (const float*)d_in[5];
    const float* b3   = (const float*)d_in[6];
    const float* bias = (const float*)d_in[7];
    float* out = (float*)d_out;

    cudaFuncSetAttribute(k_fft_x,   cudaFuncAttributeMaxDynamicSharedMemorySize, 65536);
    cudaFuncSetAttribute(k_fft_g,   cudaFuncAttributeMaxDynamicSharedMemorySize, 65536);
    cudaFuncSetAttribute(k_fft_inv, cudaFuncAttributeMaxDynamicSharedMemorySize, 65536);
    cudaFuncSetAttribute(k_cgemm,   cudaFuncAttributeMaxDynamicSharedMemorySize, 81920);

    k_twiddle<<<16, 256>>>();
    k_mlp<<<TN, HIDN>>>(w1, b1, w2, b2);
    k_fft_g<<<HIDN, 512, 65536>>>();
    k_cgemm<<<dim3(TN / 128, CTOTN / 64), 256, 81920>>>(w3);
    k_fixup<<<4, 256>>>(b3);
    k_fft_x<<<BN * CINN, 512, 65536>>>(x);
    k_contract<<<TN / 16, 256>>>();
    k_fft_inv<<<BN * COUTN, 512, 65536>>>(out, bias);
}

// round 5
// speedup vs baseline: 2.2638x; 2.2638x over previous
#include <cuda_runtime.h>
#include <math.h>

// Problem constants
#define TN    8192
#define LOGN  13
#define HIDN  64
#define BN    8
#define CINN  32
#define COUTN 32
#define CTOTN 1024   // COUT*CIN
#define NFREQ 4097   // rfft bins
#define FSTR  4104   // padded row stride (complex), mult of 8

// ---------------- device scratch ------------------------------------------------
__device__ float2 d_tw[TN / 2];                    // twiddles exp(-2*pi*i*k/N)
__device__ float  d_h2t[HIDN * TN];                // h2 transposed: [j][t]
__device__ float2 d_G[HIDN * FSTR];                // rfft(h2): [j][f], f<=4096
__device__ float2 d_Xf[(size_t)(BN * CINN) * FSTR];   // rfft(x): [(b*32+i)][f]
__device__ float2 d_Yf[(size_t)(BN * COUTN) * FSTR];  // result spectra (half)

// ---------------- twiddle table -------------------------------------------------
__global__ void k_twiddle() {
    int k = blockIdx.x * blockDim.x + threadIdx.x;
    if (k < TN / 2) {
        float s, c;
        sincospif(-2.0f * (float)k / (float)TN, &s, &c);
        d_tw[k] = make_float2(c, s);
    }
}

// ---------------- MLP: h2[t][j] -------------------------------------------------
__global__ void k_mlp(const float* __restrict__ w1, const float* __restrict__ b1,
                      const float* __restrict__ w2, const float* __restrict__ b2) {
    __shared__ float h1[HIDN];
    int t = blockIdx.x;
    int j = threadIdx.x;  // 64 threads
    float pos = (float)t * (1.0f / (float)(TN - 1));
    float z = pos * w1[j] + b1[j];
    h1[j] = 0.5f * z * (1.0f + erff(z * 0.7071067811865476f));
    __syncthreads();
    float acc = b2[j];
#pragma unroll
    for (int k = 0; k < HIDN; k++) acc += h1[k] * w2[k * HIDN + j];
    float h2 = 0.5f * acc * (1.0f + erff(acc * 0.7071067811865476f));
    d_h2t[j * TN + t] = h2;
}

// ---------------- shared-memory radix-2 FFT core (8192 pts, 512 threads) --------
__device__ __forceinline__ void fft_stages(float2* s, int tid, bool inv) {
    for (int p = 0; p < LOGN; p++) {
        int half = 1 << p;
#pragma unroll
        for (int u = 0; u < (TN / 2) / 512; u++) {
            int k  = tid + u * 512;
            int j  = k & (half - 1);
            int i0 = ((k >> p) << (p + 1)) + j;
            int i1 = i0 + half;
            float2 w = d_tw[j << (LOGN - 1 - p)];
            float wy = inv ? -w.y : w.y;
            float2 bv = s[i1];
            float2 tv = make_float2(bv.x * w.x - bv.y * wy,
                                    bv.x * wy + bv.y * w.x);
            float2 av = s[i0];
            s[i0] = make_float2(av.x + tv.x, av.y + tv.y);
            s[i1] = make_float2(av.x - tv.x, av.y - tv.y);
        }
        __syncthreads();
    }
}

// ---------------- packed real-pair forward FFT helpers --------------------------
// FFT of (ra + i*rb); unpack Hermitian halves, store f = 0..4096 only.
__device__ __forceinline__ void store_half_spectra(const float2* s, int tid,
                                                   float2* oa, float2* ob) {
#pragma unroll
    for (int u = 0; u < 8; u++) {
        int f = tid + u * 512;            // 0..4095
        float2 uu = s[f];
        float2 vv = s[(TN - f) & (TN - 1)];
        float vx = vv.x, vy = -vv.y;      // conj
        oa[f] = make_float2(0.5f * (uu.x + vx), 0.5f * (uu.y + vy));
        float wx = uu.x - vx, wyv = uu.y - vy;
        ob[f] = make_float2(0.5f * wyv, -0.5f * wx);
    }
    if (tid == 0) {
        float2 uu = s[TN / 2];
        oa[TN / 2] = make_float2(uu.x, 0.f);
        ob[TN / 2] = make_float2(uu.y, 0.f);
    }
}

// forward FFT of two real x rows at once -> d_Xf (128 blocks)
__global__ void k_fft_xp(const float* __restrict__ x) {
    extern __shared__ float2 s[];
    int tid = threadIdx.x;
    const float* ra = x + (size_t)(2 * blockIdx.x) * TN;
    const float* rb = ra + TN;
#pragma unroll
    for (int u = 0; u < TN / 512; u++) {
        int idx = tid + u * 512;
        int r = __brev(idx) >> (32 - LOGN);
        s[r] = make_float2(ra[idx], rb[idx]);
    }
    __syncthreads();
    fft_stages(s, tid, false);
    float2* oa = d_Xf + (size_t)(2 * blockIdx.x) * FSTR;
    store_half_spectra(s, tid, oa, oa + FSTR);
}

// forward FFT of two h2 rows at once -> d_G (32 blocks)
__global__ void k_fft_gp() {
    extern __shared__ float2 s[];
    int tid = threadIdx.x;
    const float* ra = d_h2t + (size_t)(2 * blockIdx.x) * TN;
    const float* rb = ra + TN;
#pragma unroll
    for (int u = 0; u < TN / 512; u++) {
        int idx = tid + u * 512;
        int r = __brev(idx) >> (32 - LOGN);
        s[r] = make_float2(ra[idx], rb[idx]);
    }
    __syncthreads();
    fft_stages(s, tid, false);
    float2* oa = d_G + (size_t)(2 * blockIdx.x) * FSTR;
    store_half_spectra(s, tid, oa, oa + FSTR);
}

// ---------------- fused filter-GEMM + contraction -------------------------------
// Per block: 8 freqs. Phase1: M[o,i] = sum_j w3[j][o*32+i]*G[j,f] (+DC b3 term)
// Phase2: Y[b,o,f] = sum_i X[b,i,f]*M[o,i]. M lives in smem, Hf never hits gmem.
#define MROWSTR 9   // complex stride per M row (pad for bank spread)

__global__ void __launch_bounds__(256, 2)
k_fused(const float* __restrict__ w3, const float* __restrict__ b3) {
    extern __shared__ float2 sm[];
    float2* Ms = sm;                  // 1024 rows x MROWSTR
    float2* Gs = sm + 1024 * MROWSTR; // [64][8]
    int f0 = blockIdx.x * 8;
    int nf = NFREQ - f0; if (nf > 8) nf = 8;
    int tid = threadIdx.x;

    for (int m = tid; m < HIDN * 8; m += 256) {
        int j = m >> 3, f = m & 7;
        Gs[m] = (f < nf) ? d_G[(size_t)j * FSTR + f0 + f] : make_float2(0.f, 0.f);
    }
    __syncthreads();

    // ---- phase 1: packed-f32x2 GEMV per channel-pair column ----
#pragma unroll 1
    for (int it = 0; it < 4; it++) {
        int c = tid + it * 256;               // c = o*32+i
        unsigned long long acc2[8];
#pragma unroll
        for (int f = 0; f < 8; f++) acc2[f] = 0ull;
        const float* wp = w3 + c;
#pragma unroll 1
        for (int j4 = 0; j4 < HIDN; j4 += 4) {
            float wv[4];
#pragma unroll
            for (int k = 0; k < 4; k++) wv[k] = wp[(j4 + k) * CTOTN];
#pragma unroll
            for (int k = 0; k < 4; k++) {
                unsigned long long wpk;
                asm("mov.b64 %0, {%1, %1};" : "=l"(wpk) : "f"(wv[k]));
                const unsigned long long* gj =
                    (const unsigned long long*)(Gs + (j4 + k) * 8);
#pragma unroll
                for (int f = 0; f < 8; f++)
                    asm("fma.rn.f32x2 %0, %1, %2, %0;"
                        : "+l"(acc2[f]) : "l"(wpk), "l"(gj[f]));
            }
        }
        int o = c >> 5, i = c & 31;
        float2* mp = Ms + (size_t)(o * 32 + (i ^ o)) * MROWSTR;
#pragma unroll
        for (int f = 0; f < 8; f++) {
            float2 af;
            asm("mov.b64 {%0, %1}, %2;" : "=f"(af.x), "=f"(af.y) : "l"(acc2[f]));
            if (f0 == 0 && f == 0) af.x += (float)TN * b3[c];
            mp[f] = af;
        }
    }
    __syncthreads();

    // ---- phase 2: contraction. warp covers 4 o x 8 b (conflict-free M reads) ----
    int l = tid & 31, wid = tid >> 5;
    int o = wid * 4 + (l >> 3);
    int b = l & 7;
    float2 acc[8];
#pragma unroll
    for (int f = 0; f < 8; f++) acc[f] = make_float2(0.f, 0.f);

#pragma unroll 1
    for (int i = 0; i < CINN; i++) {
        const float2* xr = d_Xf + (size_t)(b * CINN + i) * FSTR + f0;
        float2 xv[8];
        if (nf == 8) {
            const float4* x4 = (const float4*)xr;
#pragma unroll
            for (int q = 0; q < 4; q++) {
                float4 t = x4[q];
                xv[2 * q]     = make_float2(t.x, t.y);
                xv[2 * q + 1] = make_float2(t.z, t.w);
            }
        } else {
#pragma unroll
            for (int f = 0; f < 8; f++)
                xv[f] = (f < nf) ? xr[f] : make_float2(0.f, 0.f);
        }
        const float2* mp = Ms + (size_t)(o * 32 + (i ^ o)) * MROWSTR;
#pragma unroll
        for (int f = 0; f < 8; f++) {
            float2 m = mp[f];
            acc[f].x += xv[f].x * m.x - xv[f].y * m.y;
            acc[f].y += xv[f].x * m.y + xv[f].y * m.x;
        }
    }
    float2* yr = d_Yf + (size_t)(b * COUTN + o) * FSTR + f0;
#pragma unroll
    for (int f = 0; f < 8; f++)
        if (f < nf) yr[f] = acc[f];
}

// ---------------- packed inverse FFT: two output rows per transform -------------
__global__ void k_fft_inv(float* __restrict__ out, const float* __restrict__ bias) {
    extern __shared__ float2 s[];
    int tid = threadIdx.x;
    int b = blockIdx.x >> 4, q = blockIdx.x & 15;
    int oa = 2 * q;
    const float2* ra = d_Yf + (size_t)(b * COUTN + oa) * FSTR;
    const float2* rb = ra + FSTR;
    // build full packed spectrum Z = Ya + i*Yb from stored half (Hermitian ext.)
#pragma unroll
    for (int u = 0; u < 8; u++) {
        int f = tid + u * 512;              // 0..4095
        float2 Ya = ra[f], Yb = rb[f];
        int r1 = __brev(f) >> (32 - LOGN);
        s[r1] = make_float2(Ya.x - Yb.y, Ya.y + Yb.x);
        if (f > 0) {
            int r2 = __brev(TN - f) >> (32 - LOGN);
            s[r2] = make_float2(Ya.x + Yb.y, Yb.x - Ya.y);
        }
    }
    if (tid == 0) {
        float2 Ya = ra[TN / 2], Yb = rb[TN / 2];
        s[__brev(TN / 2) >> (32 - LOGN)] = make_float2(Ya.x - Yb.y, Ya.y + Yb.x);
    }
    __syncthreads();
    fft_stages(s, tid, true);
    const float sc = 1.0f / (float)TN;
    float ba = bias[oa], bb = bias[oa + 1];
    float* pa = out + (size_t)(b * COUTN + oa) * TN;
    float* pb = pa + TN;
#pragma unroll
    for (int u = 0; u < TN / 512; u++) {
        int t = tid + u * 512;
        float2 v = s[t];
        pa[t] = v.x * sc + ba;
        pb[t] = v.y * sc + bb;
    }
}

// ---------------- launch --------------------------------------------------------
extern "C" void kernel_launch(void* const* d_in, const int* in_sizes, int n_in,
                              void* d_out, int out_size) {
    const float* x    = (const float*)d_in[0];
    const float* w1   = (const float*)d_in[1];
    const float* b1   = (const float*)d_in[2];
    const float* w2   = (const float*)d_in[3];
    const float* b2   = (const float*)d_in[4];
    const float* w3   = (const float*)d_in[5];
    const float* b3   = (const float*)d_in[6];
    const float* bias = (const float*)d_in[7];
    float* out = (float*)d_out;

    const int fftSm   = 65536;
    const int fusedSm = (1024 * MROWSTR + HIDN * 8) * (int)sizeof(float2); // 77824

    cudaFuncSetAttribute(k_fft_xp,  cudaFuncAttributeMaxDynamicSharedMemorySize, fftSm);
    cudaFuncSetAttribute(k_fft_gp,  cudaFuncAttributeMaxDynamicSharedMemorySize, fftSm);
    cudaFuncSetAttribute(k_fft_inv, cudaFuncAttributeMaxDynamicSharedMemorySize, fftSm);
    cudaFuncSetAttribute(k_fused,   cudaFuncAttributeMaxDynamicSharedMemorySize, fusedSm);

    k_twiddle<<<16, 256>>>();
    k_mlp<<<TN, HIDN>>>(w1, b1, w2, b2);
    k_fft_gp<<<HIDN / 2, 512, fftSm>>>();
    k_fft_xp<<<BN * CINN / 2, 512, fftSm>>>(x);
    k_fused<<<(NFREQ + 7) / 8, 256, fusedSm>>>(w3, b3);
    k_fft_inv<<<BN * COUTN / 2, 512, fftSm>>>(out, bias);
}

// round 6
// speedup vs baseline: 2.9565x; 1.3060x over previous
#include <cuda_runtime.h>
#include <math.h>

// Problem constants
#define TN    8192
#define LOGN  13
#define HIDN  64
#define BN    8
#define CINN  32
#define COUTN 32
#define CTOTN 1024   // COUT*CIN
#define NFREQ 4097   // rfft bins
#define FSTR  4104   // padded row stride (complex), mult of 8

// padded smem index: one float2 of pad every 16 (conflict-free phases)
#define PADI(i) ((i) + ((i) >> 4))
#define SBUF 8704    // PADI(8191)+1 rounded: 8192 + 512

// ---------------- device scratch ------------------------------------------------
__device__ float2 d_tw[TN];                        // exp(-2*pi*i*k/N), full period
__device__ float  d_h2t[HIDN * TN];                // h2 transposed: [j][t]
__device__ float2 d_G[HIDN * FSTR];                // rfft(h2): [j][f], f<=4096
__device__ float2 d_Xf[(size_t)(BN * CINN) * FSTR];   // rfft(x)
__device__ float2 d_Yf[(size_t)(BN * COUTN) * FSTR];  // result spectra (half)

// ---------------- complex helpers -----------------------------------------------
__device__ __forceinline__ float2 cadd(float2 a, float2 b) { return make_float2(a.x + b.x, a.y + b.y); }
__device__ __forceinline__ float2 csub(float2 a, float2 b) { return make_float2(a.x - b.x, a.y - b.y); }
__device__ __forceinline__ float2 cmul(float2 a, float2 b) {
    return make_float2(a.x * b.x - a.y * b.y, a.x * b.y + a.y * b.x);
}

// ---------------- twiddle table -------------------------------------------------
__global__ void k_twiddle() {
    int k = blockIdx.x * blockDim.x + threadIdx.x;
    if (k < TN) {
        float s, c;
        sincospif(-2.0f * (float)k / (float)TN, &s, &c);
        d_tw[k] = make_float2(c, s);
    }
}

// ---------------- MLP: h2[t][j] -------------------------------------------------
__global__ void k_mlp(const float* __restrict__ w1, const float* __restrict__ b1,
                      const float* __restrict__ w2, const float* __restrict__ b2) {
    __shared__ float h1[4][HIDN];
    int g = threadIdx.x >> 6;      // 0..3
    int j = threadIdx.x & 63;
    int t = blockIdx.x * 4 + g;
    float pos = (float)t * (1.0f / (float)(TN - 1));
    float z = pos * w1[j] + b1[j];
    h1[g][j] = 0.5f * z * (1.0f + erff(z * 0.7071067811865476f));
    __syncthreads();
    float acc = b2[j];
#pragma unroll
    for (int k = 0; k < HIDN; k++) acc += h1[g][k] * w2[k * HIDN + j];
    float h2 = 0.5f * acc * (1.0f + erff(acc * 0.7071067811865476f));
    d_h2t[j * TN + t] = h2;
}

// ---------------- radix-8 Stockham FFT (8192 pts, 1024 threads) -----------------
// forward DFT8 of v (already twiddled), writes y
__device__ __forceinline__ void dft8(const float2* v, float2* y) {
    const float S = 0.70710678118654752f;
    float2 a0 = cadd(v[0], v[4]), b0 = csub(v[0], v[4]);
    float2 a1 = cadd(v[1], v[5]), b1 = csub(v[1], v[5]);
    float2 a2 = cadd(v[2], v[6]), b2 = csub(v[2], v[6]);
    float2 a3 = cadd(v[3], v[7]), b3 = csub(v[3], v[7]);
    // even outputs: DFT4(a)
    float2 c0 = cadd(a0, a2), c1 = csub(a0, a2);
    float2 c2 = cadd(a1, a3), c3 = csub(a1, a3);
    y[0] = cadd(c0, c2); y[4] = csub(c0, c2);
    float2 mc3 = make_float2(c3.y, -c3.x);            // -i*c3
    y[2] = cadd(c1, mc3); y[6] = csub(c1, mc3);
    // odd outputs: DFT4(b * w8^q)
    b1 = make_float2(S * (b1.x + b1.y), S * (b1.y - b1.x));   // *w8^1
    b2 = make_float2(b2.y, -b2.x);                            // *w8^2 = -i
    b3 = make_float2(S * (b3.y - b3.x), -S * (b3.x + b3.y));  // *w8^3
    float2 d0 = cadd(b0, b2), d1 = csub(b0, b2);
    float2 d2 = cadd(b1, b3), d3 = csub(b1, b3);
    y[1] = cadd(d0, d2); y[5] = csub(d0, d2);
    float2 md3 = make_float2(d3.y, -d3.x);
    y[3] = cadd(d1, md3); y[7] = csub(d1, md3);
}

template <int LS>
__device__ __forceinline__ void pass8(const float2* __restrict__ in,
                                      float2* __restrict__ out, int t) {
    int i = t;                               // butterfly id (1024 per pass)
    int j = i & (LS - 1);
    int base = ((i & ~(LS - 1)) << 3) | j;   // (i/LS)*LS*8 + j
    float2 v[8], y[8];
#pragma unroll
    for (int q = 0; q < 8; q++) v[q] = in[PADI(i + q * 1024)];
    if (LS > 1) {
#pragma unroll
        for (int q = 1; q < 8; q++)
            v[q] = cmul(v[q], d_tw[j * q * (1024 / LS)]);
    }
    dft8(v, y);
#pragma unroll
    for (int q = 0; q < 8; q++) out[PADI(base + q * LS)] = y[q];
}

// full forward FFT: input natural order in A, result natural order in B
__device__ __forceinline__ void fft_passes(float2* A, float2* B, int t) {
    pass8<1>(A, B, t);   __syncthreads();
    pass8<8>(B, A, t);   __syncthreads();
    pass8<64>(A, B, t);  __syncthreads();
    pass8<512>(B, A, t); __syncthreads();
    // final radix-2: Ls=4096
#pragma unroll
    for (int u = 0; u < 4; u++) {
        int i = t + u * 1024;
        float2 a = A[PADI(i)];
        float2 b = cmul(A[PADI(i + 4096)], d_tw[i]);
        B[PADI(i)]        = cadd(a, b);
        B[PADI(i + 4096)] = csub(a, b);
    }
    __syncthreads();
}

// ---------------- forward FFTs: G rows (blocks 0..31) + x rows (32..159) --------
__global__ void __launch_bounds__(1024, 1)
k_fft_fwd(const float* __restrict__ x) {
    extern __shared__ float2 sm[];
    float2* A = sm;
    float2* B = sm + SBUF;
    int t = threadIdx.x;
    const float* ra;
    float2* oa;
    if (blockIdx.x < HIDN / 2) {
        ra = d_h2t + (size_t)(2 * blockIdx.x) * TN;
        oa = d_G   + (size_t)(2 * blockIdx.x) * FSTR;
    } else {
        int bb = blockIdx.x - HIDN / 2;
        ra = x    + (size_t)(2 * bb) * TN;
        oa = d_Xf + (size_t)(2 * bb) * FSTR;
    }
    const float* rb = ra + TN;
#pragma unroll
    for (int u = 0; u < 8; u++) {
        int idx = t + u * 1024;
        A[PADI(idx)] = make_float2(ra[idx], rb[idx]);
    }
    __syncthreads();
    fft_passes(A, B, t);
    // unpack two real spectra, store f = 0..4096
#pragma unroll
    for (int u = 0; u < 4; u++) {
        int f = t + u * 1024;
        float2 uu = B[PADI(f)];
        float2 vv = B[PADI((TN - f) & (TN - 1))];
        float vx = vv.x, vy = -vv.y;          // conj
        oa[f] = make_float2(0.5f * (uu.x + vx), 0.5f * (uu.y + vy));
        float wx = uu.x - vx, wyv = uu.y - vy;
        oa[FSTR + f] = make_float2(0.5f * wyv, -0.5f * wx);
    }
    if (t == 0) {
        float2 uu = B[PADI(TN / 2)];
        oa[TN / 2]        = make_float2(uu.x, 0.f);
        oa[FSTR + TN / 2] = make_float2(uu.y, 0.f);
    }
}

// ---------------- fused filter-GEMM + contraction (unchanged from R4) -----------
#define MROWSTR 9

__global__ void __launch_bounds__(256, 2)
k_fused(const float* __restrict__ w3, const float* __restrict__ b3) {
    extern __shared__ float2 smf[];
    float2* Ms = smf;                  // 1024 rows x MROWSTR
    float2* Gs = smf + 1024 * MROWSTR; // [64][8]
    int f0 = blockIdx.x * 8;
    int nf = NFREQ - f0; if (nf > 8) nf = 8;
    int tid = threadIdx.x;

    for (int m = tid; m < HIDN * 8; m += 256) {
        int j = m >> 3, f = m & 7;
        Gs[m] = (f < nf) ? d_G[(size_t)j * FSTR + f0 + f] : make_float2(0.f, 0.f);
    }
    __syncthreads();

#pragma unroll 1
    for (int it = 0; it < 4; it++) {
        int c = tid + it * 256;               // c = o*32+i
        unsigned long long acc2[8];
#pragma unroll
        for (int f = 0; f < 8; f++) acc2[f] = 0ull;
        const float* wp = w3 + c;
#pragma unroll 1
        for (int j4 = 0; j4 < HIDN; j4 += 4) {
            float wv[4];
#pragma unroll
            for (int k = 0; k < 4; k++) wv[k] = wp[(j4 + k) * CTOTN];
#pragma unroll
            for (int k = 0; k < 4; k++) {
                unsigned long long wpk;
                asm("mov.b64 %0, {%1, %1};" : "=l"(wpk) : "f"(wv[k]));
                const unsigned long long* gj =
                    (const unsigned long long*)(Gs + (j4 + k) * 8);
#pragma unroll
                for (int f = 0; f < 8; f++)
                    asm("fma.rn.f32x2 %0, %1, %2, %0;"
                        : "+l"(acc2[f]) : "l"(wpk), "l"(gj[f]));
            }
        }
        int o = c >> 5, i = c & 31;
        float2* mp = Ms + (size_t)(o * 32 + (i ^ o)) * MROWSTR;
#pragma unroll
        for (int f = 0; f < 8; f++) {
            float2 af;
            asm("mov.b64 {%0, %1}, %2;" : "=f"(af.x), "=f"(af.y) : "l"(acc2[f]));
            if (f0 == 0 && f == 0) af.x += (float)TN * b3[c];
            mp[f] = af;
        }
    }
    __syncthreads();

    int l = tid & 31, wid = tid >> 5;
    int o = wid * 4 + (l >> 3);
    int b = l & 7;
    float2 acc[8];
#pragma unroll
    for (int f = 0; f < 8; f++) acc[f] = make_float2(0.f, 0.f);

#pragma unroll 1
    for (int i = 0; i < CINN; i++) {
        const float2* xr = d_Xf + (size_t)(b * CINN + i) * FSTR + f0;
        float2 xv[8];
        if (nf == 8) {
            const float4* x4 = (const float4*)xr;
#pragma unroll
            for (int q = 0; q < 4; q++) {
                float4 tq = x4[q];
                xv[2 * q]     = make_float2(tq.x, tq.y);
                xv[2 * q + 1] = make_float2(tq.z, tq.w);
            }
        } else {
#pragma unroll
            for (int f = 0; f < 8; f++)
                xv[f] = (f < nf) ? xr[f] : make_float2(0.f, 0.f);
        }
        const float2* mp = Ms + (size_t)(o * 32 + (i ^ o)) * MROWSTR;
#pragma unroll
        for (int f = 0; f < 8; f++) {
            float2 m = mp[f];
            acc[f].x += xv[f].x * m.x - xv[f].y * m.y;
            acc[f].y += xv[f].x * m.y + xv[f].y * m.x;
        }
    }
    float2* yr = d_Yf + (size_t)(b * COUTN + o) * FSTR + f0;
#pragma unroll
    for (int f = 0; f < 8; f++)
        if (f < nf) yr[f] = acc[f];
}

// ---------------- packed inverse FFT via conj(forward(conj)) --------------------
__global__ void __launch_bounds__(1024, 1)
k_fft_inv(float* __restrict__ out, const float* __restrict__ bias) {
    extern __shared__ float2 sm[];
    float2* A = sm;
    float2* B = sm + SBUF;
    int t = threadIdx.x;
    int b = blockIdx.x >> 4, q = blockIdx.x & 15;
    int oc = 2 * q;
    const float2* ra = d_Yf + (size_t)(b * COUTN + oc) * FSTR;
    const float2* rb = ra + FSTR;
    // build conj of packed spectrum Z = Ya + i*Yb (Hermitian extension)
#pragma unroll
    for (int u = 0; u < 4; u++) {
        int f = t + u * 1024;              // 0..4095
        float2 Ya = ra[f], Yb = rb[f];
        A[PADI(f)] = make_float2(Ya.x - Yb.y, -(Ya.y + Yb.x));
        if (f > 0)
            A[PADI(TN - f)] = make_float2(Ya.x + Yb.y, Ya.y - Yb.x);
    }
    if (t == 0) {
        float2 Ya = ra[TN / 2], Yb = rb[TN / 2];
        A[PADI(TN / 2)] = make_float2(Ya.x - Yb.y, -(Ya.y + Yb.x));
    }
    __syncthreads();
    fft_passes(A, B, t);   // forward FFT of conj(Z)
    const float sc = 1.0f / (float)TN;
    float ba = bias[oc], bb = bias[oc + 1];
    float* pa = out + (size_t)(b * COUTN + oc) * TN;
    float* pb = pa + TN;
#pragma unroll
    for (int u = 0; u < 8; u++) {
        int i = t + u * 1024;
        float2 v = B[PADI(i)];
        pa[i] =  v.x * sc + ba;    // Re(conj(fft)) = Re
        pb[i] = -v.y * sc + bb;    // Im(conj(fft)) = -Im
    }
}

// ---------------- launch --------------------------------------------------------
extern "C" void kernel_launch(void* const* d_in, const int* in_sizes, int n_in,
                              void* d_out, int out_size) {
    const float* x    = (const float*)d_in[0];
    const float* w1   = (const float*)d_in[1];
    const float* b1   = (const float*)d_in[2];
    const float* w2   = (const float*)d_in[3];
    const float* b2   = (const float*)d_in[4];
    const float* w3   = (const float*)d_in[5];
    const float* b3   = (const float*)d_in[6];
    const float* bias = (const float*)d_in[7];
    float* out = (float*)d_out;

    const int fftSm   = 2 * SBUF * (int)sizeof(float2);                    // 139264
    const int fusedSm = (1024 * MROWSTR + HIDN * 8) * (int)sizeof(float2); // 77824

    cudaFuncSetAttribute(k_fft_fwd, cudaFuncAttributeMaxDynamicSharedMemorySize, fftSm);
    cudaFuncSetAttribute(k_fft_inv, cudaFuncAttributeMaxDynamicSharedMemorySize, fftSm);
    cudaFuncSetAttribute(k_fused,   cudaFuncAttributeMaxDynamicSharedMemorySize, fusedSm);

    k_twiddle<<<32, 256>>>();
    k_mlp<<<TN / 4, 256>>>(w1, b1, w2, b2);
    k_fft_fwd<<<HIDN / 2 + BN * CINN / 2, 1024, fftSm>>>(x);
    k_fused<<<(NFREQ + 7) / 8, 256, fusedSm>>>(w3, b3);
    k_fft_inv<<<BN * COUTN / 2, 1024, fftSm>>>(out, bias);
}

// round 7
// speedup vs baseline: 4.4691x; 1.5116x over previous
#include <cuda_runtime.h>
#include <math.h>

// Problem constants
#define TN    8192
#define LOGN  13
#define HIDN  64
#define BN    8
#define CINN  32
#define COUTN 32
#define CTOTN 1024   // COUT*CIN
#define NFREQ 4097   // rfft bins
#define FSTR  4104   // padded row stride (complex), mult of 8

// padded smem index: one float2 of pad every 16 (conflict-free phases)
#define PADI(i) ((i) + ((i) >> 4))
#define SBUF 8704

// ---------------- device scratch ------------------------------------------------
__device__ float2 d_tw[TN];                        // exp(-2*pi*i*k/N)
__device__ float  d_h2t[HIDN * TN];                // h2 transposed: [j][t]
__device__ float2 d_G[HIDN * FSTR];                // rfft(h2)
__device__ float2 d_Xf[(size_t)(BN * CINN) * FSTR];   // rfft(x)
__device__ float2 d_Yf[(size_t)(BN * COUTN) * FSTR];  // result spectra (half)

// ---------------- complex helpers -----------------------------------------------
__device__ __forceinline__ float2 cadd(float2 a, float2 b) { return make_float2(a.x + b.x, a.y + b.y); }
__device__ __forceinline__ float2 csub(float2 a, float2 b) { return make_float2(a.x - b.x, a.y - b.y); }
__device__ __forceinline__ float2 cmul(float2 a, float2 b) {
    return make_float2(a.x * b.x - a.y * b.y, a.x * b.y + a.y * b.x);
}

// ---------------- twiddle table -------------------------------------------------
__global__ void k_twiddle() {
    int k = blockIdx.x * blockDim.x + threadIdx.x;
    if (k < TN) {
        float s, c;
        sincospif(-2.0f * (float)k / (float)TN, &s, &c);
        d_tw[k] = make_float2(c, s);
    }
}

// ---------------- MLP -----------------------------------------------------------
__global__ void k_mlp(const float* __restrict__ w1, const float* __restrict__ b1,
                      const float* __restrict__ w2, const float* __restrict__ b2) {
    __shared__ float h1[4][HIDN];
    int g = threadIdx.x >> 6;
    int j = threadIdx.x & 63;
    int t = blockIdx.x * 4 + g;
    float pos = (float)t * (1.0f / (float)(TN - 1));
    float z = pos * w1[j] + b1[j];
    h1[g][j] = 0.5f * z * (1.0f + erff(z * 0.7071067811865476f));
    __syncthreads();
    float acc = b2[j];
#pragma unroll
    for (int k = 0; k < HIDN; k++) acc += h1[g][k] * w2[k * HIDN + j];
    float h2 = 0.5f * acc * (1.0f + erff(acc * 0.7071067811865476f));
    d_h2t[j * TN + t] = h2;
}

// ---------------- radix-8 Stockham FFT (8192 pts, 1024 threads) -----------------
__device__ __forceinline__ void dft8(const float2* v, float2* y) {
    const float S = 0.70710678118654752f;
    float2 a0 = cadd(v[0], v[4]), b0 = csub(v[0], v[4]);
    float2 a1 = cadd(v[1], v[5]), b1 = csub(v[1], v[5]);
    float2 a2 = cadd(v[2], v[6]), b2 = csub(v[2], v[6]);
    float2 a3 = cadd(v[3], v[7]), b3 = csub(v[3], v[7]);
    float2 c0 = cadd(a0, a2), c1 = csub(a0, a2);
    float2 c2 = cadd(a1, a3), c3 = csub(a1, a3);
    y[0] = cadd(c0, c2); y[4] = csub(c0, c2);
    float2 mc3 = make_float2(c3.y, -c3.x);
    y[2] = cadd(c1, mc3); y[6] = csub(c1, mc3);
    b1 = make_float2(S * (b1.x + b1.y), S * (b1.y - b1.x));
    b2 = make_float2(b2.y, -b2.x);
    b3 = make_float2(S * (b3.y - b3.x), -S * (b3.x + b3.y));
    float2 d0 = cadd(b0, b2), d1 = csub(b0, b2);
    float2 d2 = cadd(b1, b3), d3 = csub(b1, b3);
    y[1] = cadd(d0, d2); y[5] = csub(d0, d2);
    float2 md3 = make_float2(d3.y, -d3.x);
    y[3] = cadd(d1, md3); y[7] = csub(d1, md3);
}

template <int LS>
__device__ __forceinline__ void pass8(const float2* __restrict__ in,
                                      float2* __restrict__ out, int t) {
    int i = t;
    int j = i & (LS - 1);
    int base = ((i & ~(LS - 1)) << 3) | j;
    float2 v[8], y[8];
#pragma unroll
    for (int q = 0; q < 8; q++) v[q] = in[PADI(i + q * 1024)];
    if (LS > 1) {
#pragma unroll
        for (int q = 1; q < 8; q++)
            v[q] = cmul(v[q], d_tw[j * q * (1024 / LS)]);
    }
    dft8(v, y);
#pragma unroll
    for (int q = 0; q < 8; q++) out[PADI(base + q * LS)] = y[q];
}

__device__ __forceinline__ void fft_passes(float2* A, float2* B, int t) {
    pass8<1>(A, B, t);   __syncthreads();
    pass8<8>(B, A, t);   __syncthreads();
    pass8<64>(A, B, t);  __syncthreads();
    pass8<512>(B, A, t); __syncthreads();
#pragma unroll
    for (int u = 0; u < 4; u++) {
        int i = t + u * 1024;
        float2 a = A[PADI(i)];
        float2 b = cmul(A[PADI(i + 4096)], d_tw[i]);
        B[PADI(i)]        = cadd(a, b);
        B[PADI(i + 4096)] = csub(a, b);
    }
    __syncthreads();
}

// ---------------- forward FFTs: G rows (blocks 0..31) + x rows (32..159) --------
__global__ void __launch_bounds__(1024, 1)
k_fft_fwd(const float* __restrict__ x) {
    extern __shared__ float2 sm[];
    float2* A = sm;
    float2* B = sm + SBUF;
    int t = threadIdx.x;
    const float* ra;
    float2* oa;
    if (blockIdx.x < HIDN / 2) {
        ra = d_h2t + (size_t)(2 * blockIdx.x) * TN;
        oa = d_G   + (size_t)(2 * blockIdx.x) * FSTR;
    } else {
        int bb = blockIdx.x - HIDN / 2;
        ra = x    + (size_t)(2 * bb) * TN;
        oa = d_Xf + (size_t)(2 * bb) * FSTR;
    }
    const float* rb = ra + TN;
#pragma unroll
    for (int u = 0; u < 8; u++) {
        int idx = t + u * 1024;
        A[PADI(idx)] = make_float2(ra[idx], rb[idx]);
    }
    __syncthreads();
    fft_passes(A, B, t);
#pragma unroll
    for (int u = 0; u < 4; u++) {
        int f = t + u * 1024;
        float2 uu = B[PADI(f)];
        float2 vv = B[PADI((TN - f) & (TN - 1))];
        float vx = vv.x, vy = -vv.y;
        oa[f] = make_float2(0.5f * (uu.x + vx), 0.5f * (uu.y + vy));
        float wx = uu.x - vx, wyv = uu.y - vy;
        oa[FSTR + f] = make_float2(0.5f * wyv, -0.5f * wx);
    }
    if (t == 0) {
        float2 uu = B[PADI(TN / 2)];
        oa[TN / 2]        = make_float2(uu.x, 0.f);
        oa[FSTR + TN / 2] = make_float2(uu.y, 0.f);
    }
}

// ---------------- fused filter-GEMM + contraction (register-tiled) --------------
// Per block: 8 freqs.
// Phase1: M[c][f] = sum_j w3[j][c]*G[j][f] (+DC b3), thread = 16c x 2f (c-pair f32x2)
// Phase2: Y[b][o][f] = sum_i Xs[b][i][f]*M[o*32+i][f], thread = 2o x 2b x 2f
#define MROWSTR 9    // Ms row stride (float2)
#define XROWSTR 66   // Xs i-row stride (float2), even for LDS.128 alignment

__global__ void __launch_bounds__(256)
k_fused(const float* __restrict__ w3, const float* __restrict__ b3) {
    extern __shared__ float2 smf[];
    float2* Ms = smf;                        // [1024][MROWSTR]
    float2* Gs = smf + 1024 * MROWSTR;       // [64][8]
    float2* Xs = Gs + HIDN * 8;              // [32 i][XROWSTR], idx = i*66 + b*8 + f
    int f0 = blockIdx.x * 8;
    int nf = NFREQ - f0; if (nf > 8) nf = 8;
    int tid = threadIdx.x;

    // ---- stage G tile ----
    for (int m = tid; m < HIDN * 8; m += 256) {
        int j = m >> 3, f = m & 7;
        Gs[m] = (f < nf) ? d_G[(size_t)j * FSTR + f0 + f] : make_float2(0.f, 0.f);
    }
    // ---- stage X tile: row m = b*32+i ----
    {
        int b = tid >> 5, i = tid & 31;
        const float2* xr = d_Xf + (size_t)tid * FSTR + f0;
        float2* xd = Xs + i * XROWSTR + b * 8;
        if (nf == 8) {
            const float4* x4 = (const float4*)xr;
            float4* d4 = (float4*)xd;
#pragma unroll
            for (int q = 0; q < 4; q++) d4[q] = x4[q];
        } else {
#pragma unroll
            for (int f = 0; f < 8; f++)
                xd[f] = (f < nf) ? xr[f] : make_float2(0.f, 0.f);
        }
    }
    __syncthreads();

    // ---- phase 1 ----
    {
        int tm = tid >> 2;          // 0..63 : c-block of 16
        int tf = tid & 3;           // 0..3  : f-pair
        unsigned long long accR[8][2], accI[8][2];   // [c-pair][f-slot]
#pragma unroll
        for (int p = 0; p < 8; p++) {
            accR[p][0] = accR[p][1] = 0ull;
            accI[p][0] = accI[p][1] = 0ull;
        }
        const float* wp = w3 + tm * 16;
        const float2* gp = Gs + tf * 2;
#pragma unroll 2
        for (int j = 0; j < HIDN; j++) {
            // g for the 2 f-slots: one LDS.128
            float4 gq = *(const float4*)(gp + j * 8);
            unsigned long long gx0, gy0, gx1, gy1;
            asm("mov.b64 %0, {%1, %1};" : "=l"(gx0) : "f"(gq.x));
            asm("mov.b64 %0, {%1, %1};" : "=l"(gy0) : "f"(gq.y));
            asm("mov.b64 %0, {%1, %1};" : "=l"(gx1) : "f"(gq.z));
            asm("mov.b64 %0, {%1, %1};" : "=l"(gy1) : "f"(gq.w));
            // 16 w values = 4 LDG.128 = 8 packed c-pairs
            const float4* w4 = (const float4*)(wp + j * CTOTN);
#pragma unroll
            for (int q = 0; q < 4; q++) {
                float4 wv = w4[q];
                unsigned long long wp0, wp1;
                asm("mov.b64 %0, {%1, %2};" : "=l"(wp0) : "f"(wv.x), "f"(wv.y));
                asm("mov.b64 %0, {%1, %2};" : "=l"(wp1) : "f"(wv.z), "f"(wv.w));
                asm("fma.rn.f32x2 %0, %1, %2, %0;" : "+l"(accR[2*q  ][0]) : "l"(wp0), "l"(gx0));
                asm("fma.rn.f32x2 %0, %1, %2, %0;" : "+l"(accI[2*q  ][0]) : "l"(wp0), "l"(gy0));
                asm("fma.rn.f32x2 %0, %1, %2, %0;" : "+l"(accR[2*q  ][1]) : "l"(wp0), "l"(gx1));
                asm("fma.rn.f32x2 %0, %1, %2, %0;" : "+l"(accI[2*q  ][1]) : "l"(wp0), "l"(gy1));
                asm("fma.rn.f32x2 %0, %1, %2, %0;" : "+l"(accR[2*q+1][0]) : "l"(wp1), "l"(gx0));
                asm("fma.rn.f32x2 %0, %1, %2, %0;" : "+l"(accI[2*q+1][0]) : "l"(wp1), "l"(gy0));
                asm("fma.rn.f32x2 %0, %1, %2, %0;" : "+l"(accR[2*q+1][1]) : "l"(wp1), "l"(gx1));
                asm("fma.rn.f32x2 %0, %1, %2, %0;" : "+l"(accI[2*q+1][1]) : "l"(wp1), "l"(gy1));
            }
        }
        // write Ms with XOR-swizzled rows
#pragma unroll
        for (int p = 0; p < 8; p++) {
#pragma unroll
            for (int fs = 0; fs < 2; fs++) {
                float r0, r1, i0, i1;
                asm("mov.b64 {%0, %1}, %2;" : "=f"(r0), "=f"(r1) : "l"(accR[p][fs]));
                asm("mov.b64 {%0, %1}, %2;" : "=f"(i0), "=f"(i1) : "l"(accI[p][fs]));
                int c0 = tm * 16 + p * 2;
                if (f0 == 0 && tf == 0 && fs == 0) {
                    r0 += (float)TN * b3[c0];
                    r1 += (float)TN * b3[c0 + 1];
                }
                int f = tf * 2 + fs;
                int o0 = c0 >> 5, ii0 = c0 & 31;
                Ms[(o0 * 32 + (ii0 ^ o0)) * MROWSTR + f]       = make_float2(r0, i0);
                Ms[(o0 * 32 + ((ii0 + 1) ^ o0)) * MROWSTR + f] = make_float2(r1, i1);
            }
        }
    }
    __syncthreads();

    // ---- phase 2 ----
    {
        int to = tid >> 4;          // 0..15 -> o = 2to+os
        int tb = (tid >> 2) & 3;    // 0..3  -> b = 2tb+bs
        int tf = tid & 3;           // 0..3  -> f = 2tf+fs
        float2 acc[2][2][2];        // [os][bs][fs]
#pragma unroll
        for (int a = 0; a < 2; a++)
#pragma unroll
            for (int bq = 0; bq < 2; bq++)
#pragma unroll
                for (int fq = 0; fq < 2; fq++) acc[a][bq][fq] = make_float2(0.f, 0.f);

#pragma unroll 2
        for (int i = 0; i < CINN; i++) {
            float2 xv[2][2];
#pragma unroll
            for (int bs = 0; bs < 2; bs++) {
                float4 xq = *(const float4*)(Xs + i * XROWSTR + (2 * tb + bs) * 8 + 2 * tf);
                xv[bs][0] = make_float2(xq.x, xq.y);
                xv[bs][1] = make_float2(xq.z, xq.w);
            }
            float2 mv[2][2];
#pragma unroll
            for (int os = 0; os < 2; os++) {
                int o = 2 * to + os;
                const float2* mp = Ms + (o * 32 + (i ^ o)) * MROWSTR + 2 * tf;
                mv[os][0] = mp[0];
                mv[os][1] = mp[1];
            }
#pragma unroll
            for (int os = 0; os < 2; os++)
#pragma unroll
                for (int bs = 0; bs < 2; bs++)
#pragma unroll
                    for (int fs = 0; fs < 2; fs++) {
                        float2 xq = xv[bs][fs], m = mv[os][fs];
                        acc[os][bs][fs].x += xq.x * m.x - xq.y * m.y;
                        acc[os][bs][fs].y += xq.x * m.y + xq.y * m.x;
                    }
        }
#pragma unroll
        for (int os = 0; os < 2; os++)
#pragma unroll
            for (int bs = 0; bs < 2; bs++) {
                int o = 2 * to + os, b = 2 * tb + bs;
                float2* yr = d_Yf + (size_t)(b * COUTN + o) * FSTR + f0 + 2 * tf;
#pragma unroll
                for (int fs = 0; fs < 2; fs++)
                    if (2 * tf + fs < nf) yr[fs] = acc[os][bs][fs];
            }
    }
}

// ---------------- packed inverse FFT via conj(forward(conj)) --------------------
__global__ void __launch_bounds__(1024, 1)
k_fft_inv(float* __restrict__ out, const float* __restrict__ bias) {
    extern __shared__ float2 sm[];
    float2* A = sm;
    float2* B = sm + SBUF;
    int t = threadIdx.x;
    int b = blockIdx.x >> 4, q = blockIdx.x & 15;
    int oc = 2 * q;
    const float2* ra = d_Yf + (size_t)(b * COUTN + oc) * FSTR;
    const float2* rb = ra + FSTR;
#pragma unroll
    for (int u = 0; u < 4; u++) {
        int f = t + u * 1024;
        float2 Ya = ra[f], Yb = rb[f];
        A[PADI(f)] = make_float2(Ya.x - Yb.y, -(Ya.y + Yb.x));
        if (f > 0)
            A[PADI(TN - f)] = make_float2(Ya.x + Yb.y, Ya.y - Yb.x);
    }
    if (t == 0) {
        float2 Ya = ra[TN / 2], Yb = rb[TN / 2];
        A[PADI(TN / 2)] = make_float2(Ya.x - Yb.y, -(Ya.y + Yb.x));
    }
    __syncthreads();
    fft_passes(A, B, t);
    const float sc = 1.0f / (float)TN;
    float ba = bias[oc], bb = bias[oc + 1];
    float* pa = out + (size_t)(b * COUTN + oc) * TN;
    float* pb = pa + TN;
#pragma unroll
    for (int u = 0; u < 8; u++) {
        int i = t + u * 1024;
        float2 v = B[PADI(i)];
        pa[i] =  v.x * sc + ba;
        pb[i] = -v.y * sc + bb;
    }
}

// ---------------- launch --------------------------------------------------------
extern "C" void kernel_launch(void* const* d_in, const int* in_sizes, int n_in,
                              void* d_out, int out_size) {
    const float* x    = (const float*)d_in[0];
    const float* w1   = (const float*)d_in[1];
    const float* b1   = (const float*)d_in[2];
    const float* w2   = (const float*)d_in[3];
    const float* b2   = (const float*)d_in[4];
    const float* w3   = (const float*)d_in[5];
    const float* b3   = (const float*)d_in[6];
    const float* bias = (const float*)d_in[7];
    float* out = (float*)d_out;

    const int fftSm   = 2 * SBUF * (int)sizeof(float2);   // 139264
    const int fusedSm = (1024 * MROWSTR + HIDN * 8 + 32 * XROWSTR) * (int)sizeof(float2); // 94720

    cudaFuncSetAttribute(k_fft_fwd, cudaFuncAttributeMaxDynamicSharedMemorySize, fftSm);
    cudaFuncSetAttribute(k_fft_inv, cudaFuncAttributeMaxDynamicSharedMemorySize, fftSm);
    cudaFuncSetAttribute(k_fused,   cudaFuncAttributeMaxDynamicSharedMemorySize, fusedSm);

    k_twiddle<<<32, 256>>>();
    k_mlp<<<TN / 4, 256>>>(w1, b1, w2, b2);
    k_fft_fwd<<<HIDN / 2 + BN * CINN / 2, 1024, fftSm>>>(x);
    k_fused<<<(NFREQ + 7) / 8, 256, fusedSm>>>(w3, b3);
    k_fft_inv<<<BN * COUTN / 2, 1024, fftSm>>>(out, bias);
}